// round 15
// baseline (speedup 1.0000x reference)
#include <cuda_runtime.h>
#include <cuda_fp16.h>

#define BB 4
#define SS 1024
#define DD 1024
#define HH 16
#define DKC 64
#define DFF 4096

// ---------------- scratch ----------------
__device__ __half g_xh  [BB*SS*DD];
__device__ __half g_wqkv[DD*3*DD];          // [k=1024 d][n=3072: seg*1024+h*64+dk]
__device__ __half g_wo  [DD*DD];            // [K,N]
__device__ __half g_w1  [DD*DFF];
__device__ __half g_w2  [DFF*DD];
__device__ __half g_q   [BB*HH*SS*DKC];     // [z][s][dk]
__device__ __half g_k   [BB*HH*SS*DKC];
__device__ __half g_v   [BB*HH*SS*DKC];
__device__ __half g_oc  [BB*SS*DD];
__device__ __half g_at  [BB*SS*DD];
__device__ __half g_x1h [BB*SS*DD];
__device__ __half g_ff  [BB*SS*DFF];
__device__ __half g_ps  [BB*SS*DD];

// ---------------- asm helpers ----------------
__device__ __forceinline__ void cp16(unsigned dst, const void* src) {
    asm volatile("cp.async.cg.shared.global [%0], [%1], 16;" :: "r"(dst), "l"(src));
}
__device__ __forceinline__ void cp_commit() { asm volatile("cp.async.commit_group;" ::: "memory"); }
__device__ __forceinline__ void cp_wait0()  { asm volatile("cp.async.wait_group 0;" ::: "memory"); }
__device__ __forceinline__ void cp_wait1()  { asm volatile("cp.async.wait_group 1;" ::: "memory"); }

__device__ __forceinline__ void ldm_x4(unsigned& r0, unsigned& r1, unsigned& r2, unsigned& r3, unsigned addr) {
    asm volatile("ldmatrix.sync.aligned.m8n8.x4.shared.b16 {%0,%1,%2,%3}, [%4];"
                 : "=r"(r0), "=r"(r1), "=r"(r2), "=r"(r3) : "r"(addr));
}
__device__ __forceinline__ void ldm_x4t(unsigned& r0, unsigned& r1, unsigned& r2, unsigned& r3, unsigned addr) {
    asm volatile("ldmatrix.sync.aligned.m8n8.x4.trans.shared.b16 {%0,%1,%2,%3}, [%4];"
                 : "=r"(r0), "=r"(r1), "=r"(r2), "=r"(r3) : "r"(addr));
}
__device__ __forceinline__ void ldm_x2t(unsigned& r0, unsigned& r1, unsigned addr) {
    asm volatile("ldmatrix.sync.aligned.m8n8.x2.trans.shared.b16 {%0,%1}, [%2];"
                 : "=r"(r0), "=r"(r1) : "r"(addr));
}
__device__ __forceinline__ void stm_x2(unsigned addr, unsigned r0, unsigned r1) {
    asm volatile("stmatrix.sync.aligned.m8n8.x2.shared.b16 [%0], {%1,%2};"
                 :: "r"(addr), "r"(r0), "r"(r1) : "memory");
}
__device__ __forceinline__ void mma16(float* c, const unsigned* a, const unsigned* b) {
    asm volatile(
        "mma.sync.aligned.m16n8k16.row.col.f32.f16.f16.f32 "
        "{%0,%1,%2,%3},{%4,%5,%6,%7},{%8,%9},{%0,%1,%2,%3};"
        : "+f"(c[0]), "+f"(c[1]), "+f"(c[2]), "+f"(c[3])
        : "r"(a[0]), "r"(a[1]), "r"(a[2]), "r"(a[3]), "r"(b[0]), "r"(b[1]));
}
__device__ __forceinline__ unsigned ex2h2(unsigned x) {
    unsigned r;
    asm("ex2.approx.f16x2 %0, %1;" : "=r"(r) : "r"(x));
    return r;
}

// ---------------- conversion kernels (split for fork-join overlap) ----------------
// cvt_a: x -> xh (2048 blocks) + QKV weight pack (1536 blocks). Needed immediately.
__global__ void __launch_bounds__(256)
cvt_a(const float* __restrict__ x,
      const float* __restrict__ Wq, const float* __restrict__ Wk,
      const float* __restrict__ Wv,
      __half* __restrict__ xh, __half* __restrict__ wqkv)
{
    const int tid = threadIdx.x;
    int b = blockIdx.x;

    if (b < 2048) {
        const int i = (b * 256 + tid) * 8;
        float4 v0 = *(const float4*)(x + i);
        float4 v1 = *(const float4*)(x + i + 4);
        __half2* o = (__half2*)(xh + i);
        o[0] = __floats2half2_rn(v0.x, v0.y);
        o[1] = __floats2half2_rn(v0.z, v0.w);
        o[2] = __floats2half2_rn(v1.x, v1.y);
        o[3] = __floats2half2_rn(v1.z, v1.w);
        return;
    }
    b -= 2048;
    const int c = b * 256 + tid;
    const int seg = c >> 17;
    const int r = c & 131071;
    const int d = r >> 7, h = (r >> 3) & 15, dk8 = r & 7;
    const float* src = (seg == 0 ? Wq : (seg == 1 ? Wk : Wv)) + h * 65536 + d * 64 + dk8 * 8;
    float4 a = *(const float4*)src;
    float4 bb = *(const float4*)(src + 4);
    __half2* o = (__half2*)(wqkv + d * 3072 + seg * 1024 + h * 64 + dk8 * 8);
    o[0] = __floats2half2_rn(a.x, a.y);
    o[1] = __floats2half2_rn(a.z, a.w);
    o[2] = __floats2half2_rn(bb.x, bb.y);
    o[3] = __floats2half2_rn(bb.z, bb.w);
}

// cvt_b: Wo/W1/W2 plain converts. Consumed only at O-proj/FFN — runs on a side
// stream, overlapped with QKV GEMM + flash.
__global__ void __launch_bounds__(256)
cvt_b(const float* __restrict__ Wo, const float* __restrict__ W1,
      const float* __restrict__ W2, __half* __restrict__ wo,
      __half* __restrict__ w1, __half* __restrict__ w2)
{
    const int tid = threadIdx.x;
    int b = blockIdx.x;
    const float* src; __half* dst;
    if (b < 512)       { src = Wo; dst = wo; }
    else if (b < 2560) { b -= 512; src = W1; dst = w1; }
    else               { b -= 2560; src = W2; dst = w2; }
    const int i = (b * 256 + tid) * 8;
    float4 v0 = *(const float4*)(src + i);
    float4 v1 = *(const float4*)(src + i + 4);
    __half2* o = (__half2*)(dst + i);
    o[0] = __floats2half2_rn(v0.x, v0.y);
    o[1] = __floats2half2_rn(v0.z, v0.w);
    o[2] = __floats2half2_rn(v1.x, v1.y);
    o[3] = __floats2half2_rn(v1.z, v1.w);
}

// ---------------- swizzles ----------------
__device__ __forceinline__ unsigned tswz(int row, int kbyte) {
    return (unsigned)(row * 128 + ((kbyte ^ ((row & 7) << 4)) & 127) + (kbyte & ~127));
}
__device__ __forceinline__ unsigned swz256(int row, int cb) {
    return (unsigned)(row * 256 + (cb & 128) + ((cb & 127) ^ ((row & 7) << 4)));
}

// ---------------- fp16 GEMM (exact R12/R14) ----------------
#define STG_B 32768
#define G2SM  (3*STG_B)

template<int EPI>
__global__ void __launch_bounds__(256, 2)
gemm_h2(const __half* __restrict__ A, const __half* __restrict__ B,
        const float* __restrict__ b0p, const float* __restrict__ b1p,
        const float* __restrict__ b2p, void* __restrict__ C0,
        void* __restrict__ C1, void* __restrict__ C2,
        int M, int N, int K, int relu)
{
    extern __shared__ char dsm[];
    const unsigned smB = (unsigned)__cvta_generic_to_shared(dsm);

    const int tid = threadIdx.x, lane = tid & 31, wid = tid >> 5;
    const int wm = wid & 1, wn = wid >> 1;
    const int Rb = blockIdx.y * 128;
    const int Nb = blockIdx.x * 128;
    const int nS = K >> 6;

    const int crow = tid >> 3, ckc = (tid & 7) * 16;
    const int lr = lane & 15, lhb = ((lane >> 4) << 4);
    const int vrow = (lane & 7) + ((lane >> 3) & 1) * 8;
    const int vcol = (lane >> 4) << 3;

    auto issue = [&](int it) {
        const unsigned sA = smB + (it % 3) * STG_B;
        const unsigned sB = sA + 16384;
        const __half* Ap = A + (Rb + crow) * K + it * 64 + ckc / 2;
#pragma unroll
        for (int i = 0; i < 4; i++)
            cp16(sA + tswz(crow + 32 * i, ckc), Ap + 32 * i * K);
#pragma unroll
        for (int i = 0; i < 4; i++) {
            const int c = tid + 256 * i;
            const int row = c >> 4, cb = (c & 15) * 16;
            cp16(sB + swz256(row, cb), B + (it * 64 + row) * N + Nb + (c & 15) * 8);
        }
    };

    float acc[4][4][4];
#pragma unroll
    for (int i = 0; i < 4; i++)
#pragma unroll
        for (int j = 0; j < 4; j++)
#pragma unroll
            for (int r = 0; r < 4; r++) acc[i][j][r] = 0.f;

    issue(0); cp_commit();
    issue(1); cp_commit();

    for (int it = 0; it < nS; it++) {
        cp_wait1();
        __syncthreads();
        if (it + 2 < nS) issue(it + 2);
        cp_commit();

        const unsigned sA = smB + (it % 3) * STG_B;
        const unsigned sB = sA + 16384;
#pragma unroll
        for (int s = 0; s < 4; s++) {
            const int kb = s * 32;
            const int ks = s * 16;
            unsigned af[4][4], bf[2][4];
#pragma unroll
            for (int mt = 0; mt < 4; mt++)
                ldm_x4(af[mt][0], af[mt][1], af[mt][2], af[mt][3],
                       sA + tswz(wm * 64 + mt * 16 + lr, kb + lhb));
#pragma unroll
            for (int nt2 = 0; nt2 < 2; nt2++)
                ldm_x4t(bf[nt2][0], bf[nt2][1], bf[nt2][2], bf[nt2][3],
                        sB + swz256(ks + vrow, (wn * 32 + nt2 * 16 + vcol) * 2));
#pragma unroll
            for (int mt = 0; mt < 4; mt++)
#pragma unroll
                for (int nt = 0; nt < 4; nt++) {
                    unsigned b[2] = { bf[nt >> 1][(nt & 1) * 2], bf[nt >> 1][(nt & 1) * 2 + 1] };
                    mma16(acc[mt][nt], af[mt], b);
                }
        }
    }

    const int tq = lane & 3, gq = lane >> 2;

    if (EPI == 1) {
        __syncthreads();
        __half* ep = (__half*)dsm;
#pragma unroll
        for (int mt = 0; mt < 4; mt++) {
#pragma unroll
            for (int nt = 0; nt < 4; nt++) {
                const int n0 = Nb + wn * 32 + nt * 8 + tq * 2;
                const int seg = n0 >> 10, nn = n0 & 1023;
                const float* bp = seg == 0 ? b0p : (seg == 1 ? b1p : b2p);
                const int hh = nn >> 6, dk = nn & 63;
                const float bb0 = bp[hh * 64 + dk], bb1 = bp[hh * 64 + dk + 1];
                const float alpha = (seg == 0) ? 0.125f : 1.f;
#pragma unroll
                for (int half = 0; half < 2; half++) {
                    const int r = wm * 64 + mt * 16 + gq + half * 8;
                    float v0 = (acc[mt][nt][half * 2 + 0] + bb0) * alpha;
                    float v1 = (acc[mt][nt][half * 2 + 1] + bb1) * alpha;
                    *(__half2*)&ep[r * 136 + wn * 32 + nt * 8 + tq * 2] =
                        __floats2half2_rn(v0, v1);
                }
            }
        }
        __syncthreads();
        const int bidx = Rb >> 10, sbase = Rb & 1023;
        for (int c = tid; c < 2048; c += 256) {
            const int r = c >> 4, s16 = c & 15;
            uint4 val = *(uint4*)&ep[r * 136 + s16 * 8];
            const int n = Nb + s16 * 8;
            const int seg = n >> 10, nn = n & 1023;
            const int hh = nn >> 6, dk = nn & 63;
            __half* dst = seg == 0 ? (__half*)C0 : (seg == 1 ? (__half*)C1 : (__half*)C2);
            *(uint4*)&dst[(((bidx * 16 + hh) << 10) + sbase + r) * 64 + dk] = val;
        }
        return;
    }

#pragma unroll
    for (int mt = 0; mt < 4; mt++) {
#pragma unroll
        for (int nt = 0; nt < 4; nt++) {
            const int m0 = Rb + wm * 64 + mt * 16 + gq;
            const int n0 = Nb + wn * 32 + nt * 8 + tq * 2;
            const float bb0 = b0p ? b0p[n0] : 0.f;
            const float bb1 = b0p ? b0p[n0 + 1] : 0.f;
#pragma unroll
            for (int half = 0; half < 2; half++) {
                const int m = m0 + half * 8;
                float v0 = acc[mt][nt][half * 2 + 0] + bb0;
                float v1 = acc[mt][nt][half * 2 + 1] + bb1;
                if (relu) { v0 = fmaxf(v0, 0.f); v1 = fmaxf(v1, 0.f); }
                *(__half2*)((__half*)C0 + m * N + n0) = __floats2half2_rn(v0, v1);
            }
        }
    }
}

// ---------------- fp16 flash attention v3 (exact R12/R14) ----------------
#define QST 72
#define PST 136
#define OFF_K  (128*QST)
#define OFF_V0 (2*128*QST)
#define VBUF   (128*QST)
#define OFF_P  (4*128*QST)
#define FL_SMH (OFF_P + 128*PST)
__global__ void __launch_bounds__(256, 2)
flash_h(const __half* __restrict__ Qg, const __half* __restrict__ Kg,
        const __half* __restrict__ Vg, __half* __restrict__ O)
{
    extern __shared__ __half sm[];
    const unsigned smB = (unsigned)__cvta_generic_to_shared(sm);
    const unsigned sQ = smB, sK = smB + OFF_K * 2;
    const unsigned sV0 = smB + OFF_V0 * 2, sP = smB + OFF_P * 2;

    const int tid = threadIdx.x, lane = tid & 31, wid = tid >> 5;
    const int tq = lane & 3, gq = lane >> 2;
    const int lr = lane & 15, lh = (lane >> 4) << 3;
    const int z = blockIdx.y, qt = blockIdx.x;

    const __half* Qp = Qg + (z * 1024 + qt * 128) * 64;
    const __half* Kp = Kg + z * 1024 * 64;
    const __half* Vp = Vg + z * 1024 * 64;

    auto stageT = [&](const __half* src, int kt, unsigned dst) {
#pragma unroll
        for (int i = 0; i < 4; i++) {
            const int c = tid + 256 * i;
            const int row = c >> 3, cc = (c & 7) * 8;
            cp16(dst + (row * QST + cc) * 2, src + (kt * 128 + row) * 64 + cc);
        }
    };

#pragma unroll
    for (int i = 0; i < 4; i++) {
        const int c = tid + 256 * i;
        const int row = c >> 3, cc = (c & 7) * 8;
        cp16(sQ + (row * QST + cc) * 2, Qp + row * 64 + cc);
    }
    stageT(Kp, 0, sK);
    stageT(Vp, 0, sV0);
    {
        const int buf = tid >> 7, row = tid & 127;
        uint4 ones = make_uint4(0x00003C00u, 0u, 0u, 0u);
        *(uint4*)(sm + OFF_V0 + buf * VBUF + row * QST + 64) = ones;
    }
    cp_commit(); cp_wait0();
    __syncthreads();

    float oacc[9][4];
#pragma unroll
    for (int i = 0; i < 9; i++)
#pragma unroll
        for (int j = 0; j < 4; j++) oacc[i][j] = 0.f;
    float mrow0 = -1e30f, mrow1 = -1e30f;

    const unsigned aQbase = sQ + ((wid * 16 + lr) * QST + lh) * 2;
    const unsigned aPbase = sP + ((wid * 16 + lr) * PST + lh) * 2;
    const int vrow = (lane & 7) + ((lane >> 3) & 1) * 8;
    const int vcol = (lane >> 4) << 3;

    for (int kt = 0; kt < 8; kt++) {
        const unsigned sV = sV0 + (kt & 1) * (VBUF * 2);

        float sacc[16][4];
#pragma unroll
        for (int i = 0; i < 16; i++)
#pragma unroll
            for (int j = 0; j < 4; j++) sacc[i][j] = 0.f;
#pragma unroll
        for (int k16 = 0; k16 < 4; k16++) {
            const int kb = k16 * 32;
            unsigned a[4];
            ldm_x4(a[0], a[1], a[2], a[3], aQbase + kb);
#pragma unroll
            for (int ntp = 0; ntp < 8; ntp++) {
                unsigned t0, t1, t2, t3;
                ldm_x4(t0, t1, t2, t3, sK + ((ntp * 16 + lr) * QST) * 2 + lh * 2 + kb);
                unsigned b0[2] = { t0, t2 }, b1[2] = { t1, t3 };
                mma16(sacc[2 * ntp],     a, b0);
                mma16(sacc[2 * ntp + 1], a, b1);
            }
        }

        __syncthreads();
        if (kt < 7) {
            stageT(Kp, kt + 1, sK);
            stageT(Vp, kt + 1, sV0 + ((kt + 1) & 1) * (VBUF * 2));
            cp_commit();
        }

        float m0 = -1e30f, m1 = -1e30f;
#pragma unroll
        for (int nt = 0; nt < 16; nt++) {
            m0 = fmaxf(m0, fmaxf(sacc[nt][0], sacc[nt][1]));
            m1 = fmaxf(m1, fmaxf(sacc[nt][2], sacc[nt][3]));
        }
        m0 = fmaxf(m0, __shfl_xor_sync(0xffffffffu, m0, 1));
        m0 = fmaxf(m0, __shfl_xor_sync(0xffffffffu, m0, 2));
        m1 = fmaxf(m1, __shfl_xor_sync(0xffffffffu, m1, 1));
        m1 = fmaxf(m1, __shfl_xor_sync(0xffffffffu, m1, 2));
        const float mn0 = fmaxf(mrow0, m0), mn1 = fmaxf(mrow1, m1);
        const float sc0 = __expf(mrow0 - mn0), sc1 = __expf(mrow1 - mn1);
        mrow0 = mn0; mrow1 = mn1;

        const float L2E = 1.44269504f;
        const float nm0 = mn0 * L2E, nm1 = mn1 * L2E;
        const unsigned pAddr = sP + ((wid * 16 + lr) * PST) * 2;
#pragma unroll
        for (int nt = 0; nt < 16; nt++) {
            const float y0 = fmaf(sacc[nt][0], L2E, -nm0);
            const float y1 = fmaf(sacc[nt][1], L2E, -nm0);
            const float y2 = fmaf(sacc[nt][2], L2E, -nm1);
            const float y3 = fmaf(sacc[nt][3], L2E, -nm1);
            __half2 h01 = __floats2half2_rn(y0, y1);
            __half2 h23 = __floats2half2_rn(y2, y3);
            stm_x2(pAddr + nt * 16, ex2h2(*(unsigned*)&h01), ex2h2(*(unsigned*)&h23));
        }
#pragma unroll
        for (int nt = 0; nt < 9; nt++) {
            oacc[nt][0] *= sc0; oacc[nt][1] *= sc0;
            oacc[nt][2] *= sc1; oacc[nt][3] *= sc1;
        }
        __syncwarp();

#pragma unroll
        for (int k16 = 0; k16 < 8; k16++) {
            const int k0 = k16 * 16;
            unsigned a[4];
            ldm_x4(a[0], a[1], a[2], a[3], aPbase + k16 * 32);
#pragma unroll
            for (int dk4 = 0; dk4 < 4; dk4++) {
                unsigned t0, t1, t2, t3;
                ldm_x4t(t0, t1, t2, t3,
                        sV + ((k0 + vrow) * QST + dk4 * 16 + vcol) * 2);
                unsigned b0[2] = { t0, t1 }, b1[2] = { t2, t3 };
                mma16(oacc[2 * dk4],     a, b0);
                mma16(oacc[2 * dk4 + 1], a, b1);
            }
            {
                unsigned t0, t1;
                ldm_x2t(t0, t1, sV + ((k0 + lr) * QST + 64) * 2);
                unsigned b[2] = { t0, t1 };
                mma16(oacc[8], a, b);
            }
        }

        if (kt < 7) {
            cp_wait0();
            __syncthreads();
        }
    }

    const float l0 = __shfl_sync(0xffffffffu, oacc[8][0], lane & ~3);
    const float l1 = __shfl_sync(0xffffffffu, oacc[8][2], lane & ~3);
    const float i0 = 1.f / l0, i1 = 1.f / l1;
    const int b = z >> 4, h = z & 15;
    const int s0 = qt * 128 + wid * 16 + gq;
#pragma unroll
    for (int nt = 0; nt < 8; nt++) {
        const int col = h * 64 + nt * 8 + 2 * tq;
        *(__half2*)&O[(b * 1024 + s0) * 1024 + col] =
            __floats2half2_rn(oacc[nt][0] * i0, oacc[nt][1] * i0);
        *(__half2*)&O[(b * 1024 + s0 + 8) * 1024 + col] =
            __floats2half2_rn(oacc[nt][2] * i1, oacc[nt][3] * i1);
    }
}

// ---------------- residual + LayerNorm (exact R14) ----------------
template<class TX>
__global__ void __launch_bounds__(256)
add_ln_kernel(const TX* __restrict__ x, const __half* __restrict__ t,
              const float* __restrict__ gw, const float* __restrict__ bw,
              float* __restrict__ out_f, __half* __restrict__ out_h)
{
    __shared__ float r1[8], r2[8];
    const int base = blockIdx.x * 1024;
    const int tid = threadIdx.x;
    __half2 th0 = *(const __half2*)(t + base + tid * 4);
    __half2 th1 = *(const __half2*)(t + base + tid * 4 + 2);
    float4 tv;
    { float2 a = __half22float2(th0), b = __half22float2(th1);
      tv.x = a.x; tv.y = a.y; tv.z = b.x; tv.w = b.y; }

    float s = tv.x + tv.y + tv.z + tv.w;
    float q = tv.x * tv.x + tv.y * tv.y + tv.z * tv.z + tv.w * tv.w;
#pragma unroll
    for (int o = 16; o; o >>= 1) {
        s += __shfl_xor_sync(0xffffffffu, s, o);
        q += __shfl_xor_sync(0xffffffffu, q, o);
    }
    if ((tid & 31) == 0) { r1[tid >> 5] = s; r2[tid >> 5] = q; }
    __syncthreads();
    if (tid < 32) {
        float ss = (tid < 8) ? r1[tid] : 0.f;
        float qq = (tid < 8) ? r2[tid] : 0.f;
#pragma unroll
        for (int o = 4; o; o >>= 1) {
            ss += __shfl_xor_sync(0xffffffffu, ss, o);
            qq += __shfl_xor_sync(0xffffffffu, qq, o);
        }
        if (tid == 0) { r1[0] = ss; r2[0] = qq; }
    }
    __syncthreads();
    const float mean = r1[0] * (1.f / 1024.f);
    const float var  = r2[0] * (1.f / 1024.f) - mean * mean;
    const float rstd = rsqrtf(var + 1e-5f);

    float4 xv;
    if (sizeof(TX) == 4) {
        xv = *(const float4*)((const float*)x + base + tid * 4);
    } else {
        __half2 xh0 = *(const __half2*)((const __half*)x + base + tid * 4);
        __half2 xh1 = *(const __half2*)((const __half*)x + base + tid * 4 + 2);
        float2 a = __half22float2(xh0), b = __half22float2(xh1);
        xv.x = a.x; xv.y = a.y; xv.z = b.x; xv.w = b.y;
    }
    float4 gv = *(const float4*)(gw + tid * 4);
    float4 bv = *(const float4*)(bw + tid * 4);
    float4 o;
    o.x = xv.x + (tv.x - mean) * rstd * gv.x + bv.x;
    o.y = xv.y + (tv.y - mean) * rstd * gv.y + bv.y;
    o.z = xv.z + (tv.z - mean) * rstd * gv.z + bv.z;
    o.w = xv.w + (tv.w - mean) * rstd * gv.w + bv.w;
    if (out_f)
        *(float4*)(out_f + base + tid * 4) = o;
    if (out_h) {
        __half2* oh = (__half2*)(out_h + base + tid * 4);
        oh[0] = __floats2half2_rn(o.x, o.y);
        oh[1] = __floats2half2_rn(o.z, o.w);
    }
}

// ---------------- launch ----------------
template<class T>
static T* sym_addr(const void* s) {
    void* p = nullptr;
    cudaGetSymbolAddress(&p, s);
    return (T*)p;
}

extern "C" void kernel_launch(void* const* d_in, const int* in_sizes, int n_in,
                              void* d_out, int out_size)
{
    (void)in_sizes; (void)n_in; (void)out_size;
    const float* x   = (const float*)d_in[0];
    const float* Wq  = (const float*)d_in[1];
    const float* bq  = (const float*)d_in[2];
    const float* Wk  = (const float*)d_in[3];
    const float* bk  = (const float*)d_in[4];
    const float* Wv  = (const float*)d_in[5];
    const float* bv  = (const float*)d_in[6];
    const float* Wo  = (const float*)d_in[7];
    const float* bo  = (const float*)d_in[8];
    const float* W1  = (const float*)d_in[9];
    const float* b1  = (const float*)d_in[10];
    const float* W2  = (const float*)d_in[11];
    const float* b2  = (const float*)d_in[12];
    const float* g1  = (const float*)d_in[13];
    const float* be1 = (const float*)d_in[14];
    const float* g2  = (const float*)d_in[15];
    const float* be2 = (const float*)d_in[16];
    float* out = (float*)d_out;

    __half* xh   = sym_addr<__half>(g_xh);
    __half* wqkv = sym_addr<__half>(g_wqkv);
    __half* wo   = sym_addr<__half>(g_wo);
    __half* w1   = sym_addr<__half>(g_w1);
    __half* w2   = sym_addr<__half>(g_w2);
    __half* q    = sym_addr<__half>(g_q);
    __half* k    = sym_addr<__half>(g_k);
    __half* v    = sym_addr<__half>(g_v);
    __half* oc   = sym_addr<__half>(g_oc);
    __half* at   = sym_addr<__half>(g_at);
    __half* x1h  = sym_addr<__half>(g_x1h);
    __half* ff   = sym_addr<__half>(g_ff);
    __half* ps   = sym_addr<__half>(g_ps);

    static cudaStream_t s2 = nullptr;
    static cudaEvent_t evFork = nullptr, evJoin = nullptr;
    if (!s2) {
        cudaStreamCreateWithFlags(&s2, cudaStreamNonBlocking);
        cudaEventCreateWithFlags(&evFork, cudaEventDisableTiming);
        cudaEventCreateWithFlags(&evJoin, cudaEventDisableTiming);
    }

    const int FSM = FL_SMH * 2;
    cudaFuncSetAttribute(gemm_h2<0>, cudaFuncAttributeMaxDynamicSharedMemorySize, G2SM);
    cudaFuncSetAttribute(gemm_h2<1>, cudaFuncAttributeMaxDynamicSharedMemorySize, G2SM);
    cudaFuncSetAttribute(flash_h,    cudaFuncAttributeMaxDynamicSharedMemorySize, FSM);

    const dim3 blk(256);

    // fork: Wo/W1/W2 conversion on side stream, overlapped with QKV+flash
    cudaEventRecord(evFork, 0);
    cudaStreamWaitEvent(s2, evFork, 0);
    cvt_b<<<4608, blk, 0, s2>>>(Wo, W1, W2, wo, w1, w2);
    cudaEventRecord(evJoin, s2);

    // main stream
    cvt_a<<<3584, blk>>>(x, Wq, Wk, Wv, xh, wqkv);
    gemm_h2<1><<<dim3(24, 32), blk, G2SM>>>(xh, wqkv, bq, bk, bv,
                                            q, k, v, 4096, 3072, 1024, 0);
    flash_h<<<dim3(8, 64), blk, FSM>>>(q, k, v, oc);

    // join before first consumer of wo/w1/w2
    cudaStreamWaitEvent(0, evJoin, 0);

    gemm_h2<0><<<dim3(8, 32), blk, G2SM>>>(oc, wo, bo, nullptr, nullptr,
                                           at, nullptr, nullptr, 4096, 1024, 1024, 0);
    add_ln_kernel<float><<<4096, blk>>>(x, at, g1, be1, nullptr, x1h);

    gemm_h2<0><<<dim3(32, 32), blk, G2SM>>>(x1h, w1, b1, nullptr, nullptr,
                                            ff, nullptr, nullptr, 4096, 4096, 1024, 1);
    gemm_h2<0><<<dim3(8, 32), blk, G2SM>>>(ff, w2, b2, nullptr, nullptr,
                                           ps, nullptr, nullptr, 4096, 1024, 4096, 0);

    add_ln_kernel<__half><<<4096, blk>>>(x1h, ps, g2, be2, out, nullptr);
}

// round 16
// speedup vs baseline: 1.0056x; 1.0056x over previous
#include <cuda_runtime.h>
#include <cuda_fp16.h>

#define BB 4
#define SS 1024
#define DD 1024
#define HH 16
#define DKC 64
#define DFF 4096

// ---------------- scratch ----------------
__device__ __half g_xh  [BB*SS*DD];
__device__ __half g_wqkv[DD*3*DD];          // [k=1024 d][n=3072: seg*1024+h*64+dk]
__device__ __half g_wo  [DD*DD];            // [K,N]
__device__ __half g_w1  [DD*DFF];
__device__ __half g_w2  [DFF*DD];
__device__ __half g_q   [BB*HH*SS*DKC];     // [z][s][dk]
__device__ __half g_k   [BB*HH*SS*DKC];
__device__ __half g_v   [BB*HH*SS*DKC];
__device__ __half g_oc  [BB*SS*DD];
__device__ __half g_at  [BB*SS*DD];
__device__ __half g_x1h [BB*SS*DD];
__device__ __half g_ff  [BB*SS*DFF];
__device__ __half g_ps  [BB*SS*DD];

// ---------------- asm helpers ----------------
__device__ __forceinline__ void cp16(unsigned dst, const void* src) {
    asm volatile("cp.async.cg.shared.global [%0], [%1], 16;" :: "r"(dst), "l"(src));
}
__device__ __forceinline__ void cp_commit() { asm volatile("cp.async.commit_group;" ::: "memory"); }
__device__ __forceinline__ void cp_wait0()  { asm volatile("cp.async.wait_group 0;" ::: "memory"); }
__device__ __forceinline__ void cp_wait1()  { asm volatile("cp.async.wait_group 1;" ::: "memory"); }

__device__ __forceinline__ void ldm_x4(unsigned& r0, unsigned& r1, unsigned& r2, unsigned& r3, unsigned addr) {
    asm volatile("ldmatrix.sync.aligned.m8n8.x4.shared.b16 {%0,%1,%2,%3}, [%4];"
                 : "=r"(r0), "=r"(r1), "=r"(r2), "=r"(r3) : "r"(addr));
}
__device__ __forceinline__ void ldm_x4t(unsigned& r0, unsigned& r1, unsigned& r2, unsigned& r3, unsigned addr) {
    asm volatile("ldmatrix.sync.aligned.m8n8.x4.trans.shared.b16 {%0,%1,%2,%3}, [%4];"
                 : "=r"(r0), "=r"(r1), "=r"(r2), "=r"(r3) : "r"(addr));
}
__device__ __forceinline__ void ldm_x2t(unsigned& r0, unsigned& r1, unsigned addr) {
    asm volatile("ldmatrix.sync.aligned.m8n8.x2.trans.shared.b16 {%0,%1}, [%2];"
                 : "=r"(r0), "=r"(r1) : "r"(addr));
}
__device__ __forceinline__ void stm_x2(unsigned addr, unsigned r0, unsigned r1) {
    asm volatile("stmatrix.sync.aligned.m8n8.x2.shared.b16 [%0], {%1,%2};"
                 :: "r"(addr), "r"(r0), "r"(r1) : "memory");
}
__device__ __forceinline__ void mma16(float* c, const unsigned* a, const unsigned* b) {
    asm volatile(
        "mma.sync.aligned.m16n8k16.row.col.f32.f16.f16.f32 "
        "{%0,%1,%2,%3},{%4,%5,%6,%7},{%8,%9},{%0,%1,%2,%3};"
        : "+f"(c[0]), "+f"(c[1]), "+f"(c[2]), "+f"(c[3])
        : "r"(a[0]), "r"(a[1]), "r"(a[2]), "r"(a[3]), "r"(b[0]), "r"(b[1]));
}
__device__ __forceinline__ unsigned ex2h2(unsigned x) {
    unsigned r;
    asm("ex2.approx.f16x2 %0, %1;" : "=r"(r) : "r"(x));
    return r;
}

// ---------------- conversion kernels ----------------
__global__ void __launch_bounds__(256)
cvt_a(const float* __restrict__ x,
      const float* __restrict__ Wq, const float* __restrict__ Wk,
      const float* __restrict__ Wv,
      __half* __restrict__ xh, __half* __restrict__ wqkv)
{
    const int tid = threadIdx.x;
    int b = blockIdx.x;

    if (b < 2048) {
        const int i = (b * 256 + tid) * 8;
        float4 v0 = *(const float4*)(x + i);
        float4 v1 = *(const float4*)(x + i + 4);
        __half2* o = (__half2*)(xh + i);
        o[0] = __floats2half2_rn(v0.x, v0.y);
        o[1] = __floats2half2_rn(v0.z, v0.w);
        o[2] = __floats2half2_rn(v1.x, v1.y);
        o[3] = __floats2half2_rn(v1.z, v1.w);
        return;
    }
    b -= 2048;
    const int c = b * 256 + tid;
    const int seg = c >> 17;
    const int r = c & 131071;
    const int d = r >> 7, h = (r >> 3) & 15, dk8 = r & 7;
    const float* src = (seg == 0 ? Wq : (seg == 1 ? Wk : Wv)) + h * 65536 + d * 64 + dk8 * 8;
    float4 a = *(const float4*)src;
    float4 bb = *(const float4*)(src + 4);
    __half2* o = (__half2*)(wqkv + d * 3072 + seg * 1024 + h * 64 + dk8 * 8);
    o[0] = __floats2half2_rn(a.x, a.y);
    o[1] = __floats2half2_rn(a.z, a.w);
    o[2] = __floats2half2_rn(bb.x, bb.y);
    o[3] = __floats2half2_rn(bb.z, bb.w);
}

__global__ void __launch_bounds__(256)
cvt_b(const float* __restrict__ Wo, const float* __restrict__ W1,
      const float* __restrict__ W2, __half* __restrict__ wo,
      __half* __restrict__ w1, __half* __restrict__ w2)
{
    const int tid = threadIdx.x;
    int b = blockIdx.x;
    const float* src; __half* dst;
    if (b < 512)       { src = Wo; dst = wo; }
    else if (b < 2560) { b -= 512; src = W1; dst = w1; }
    else               { b -= 2560; src = W2; dst = w2; }
    const int i = (b * 256 + tid) * 8;
    float4 v0 = *(const float4*)(src + i);
    float4 v1 = *(const float4*)(src + i + 4);
    __half2* o = (__half2*)(dst + i);
    o[0] = __floats2half2_rn(v0.x, v0.y);
    o[1] = __floats2half2_rn(v0.z, v0.w);
    o[2] = __floats2half2_rn(v1.x, v1.y);
    o[3] = __floats2half2_rn(v1.z, v1.w);
}

// ---------------- swizzles ----------------
__device__ __forceinline__ unsigned tswz(int row, int kbyte) {
    return (unsigned)(row * 128 + ((kbyte ^ ((row & 7) << 4)) & 127) + (kbyte & ~127));
}
__device__ __forceinline__ unsigned swz256(int row, int cb) {
    return (unsigned)(row * 256 + (cb & 128) + ((cb & 127) ^ ((row & 7) << 4)));
}

// ---------------- fp16 GEMM (exact R12/R14) ----------------
#define STG_B 32768
#define G2SM  (3*STG_B)

template<int EPI>
__global__ void __launch_bounds__(256, 2)
gemm_h2(const __half* __restrict__ A, const __half* __restrict__ B,
        const float* __restrict__ b0p, const float* __restrict__ b1p,
        const float* __restrict__ b2p, void* __restrict__ C0,
        void* __restrict__ C1, void* __restrict__ C2,
        int M, int N, int K, int relu)
{
    extern __shared__ char dsm[];
    const unsigned smB = (unsigned)__cvta_generic_to_shared(dsm);

    const int tid = threadIdx.x, lane = tid & 31, wid = tid >> 5;
    const int wm = wid & 1, wn = wid >> 1;
    const int Rb = blockIdx.y * 128;
    const int Nb = blockIdx.x * 128;
    const int nS = K >> 6;

    const int crow = tid >> 3, ckc = (tid & 7) * 16;
    const int lr = lane & 15, lhb = ((lane >> 4) << 4);
    const int vrow = (lane & 7) + ((lane >> 3) & 1) * 8;
    const int vcol = (lane >> 4) << 3;

    auto issue = [&](int it) {
        const unsigned sA = smB + (it % 3) * STG_B;
        const unsigned sB = sA + 16384;
        const __half* Ap = A + (Rb + crow) * K + it * 64 + ckc / 2;
#pragma unroll
        for (int i = 0; i < 4; i++)
            cp16(sA + tswz(crow + 32 * i, ckc), Ap + 32 * i * K);
#pragma unroll
        for (int i = 0; i < 4; i++) {
            const int c = tid + 256 * i;
            const int row = c >> 4, cb = (c & 15) * 16;
            cp16(sB + swz256(row, cb), B + (it * 64 + row) * N + Nb + (c & 15) * 8);
        }
    };

    float acc[4][4][4];
#pragma unroll
    for (int i = 0; i < 4; i++)
#pragma unroll
        for (int j = 0; j < 4; j++)
#pragma unroll
            for (int r = 0; r < 4; r++) acc[i][j][r] = 0.f;

    issue(0); cp_commit();
    issue(1); cp_commit();

    for (int it = 0; it < nS; it++) {
        cp_wait1();
        __syncthreads();
        if (it + 2 < nS) issue(it + 2);
        cp_commit();

        const unsigned sA = smB + (it % 3) * STG_B;
        const unsigned sB = sA + 16384;
#pragma unroll
        for (int s = 0; s < 4; s++) {
            const int kb = s * 32;
            const int ks = s * 16;
            unsigned af[4][4], bf[2][4];
#pragma unroll
            for (int mt = 0; mt < 4; mt++)
                ldm_x4(af[mt][0], af[mt][1], af[mt][2], af[mt][3],
                       sA + tswz(wm * 64 + mt * 16 + lr, kb + lhb));
#pragma unroll
            for (int nt2 = 0; nt2 < 2; nt2++)
                ldm_x4t(bf[nt2][0], bf[nt2][1], bf[nt2][2], bf[nt2][3],
                        sB + swz256(ks + vrow, (wn * 32 + nt2 * 16 + vcol) * 2));
#pragma unroll
            for (int mt = 0; mt < 4; mt++)
#pragma unroll
                for (int nt = 0; nt < 4; nt++) {
                    unsigned b[2] = { bf[nt >> 1][(nt & 1) * 2], bf[nt >> 1][(nt & 1) * 2 + 1] };
                    mma16(acc[mt][nt], af[mt], b);
                }
        }
    }

    const int tq = lane & 3, gq = lane >> 2;

    if (EPI == 1) {
        __syncthreads();
        __half* ep = (__half*)dsm;
#pragma unroll
        for (int mt = 0; mt < 4; mt++) {
#pragma unroll
            for (int nt = 0; nt < 4; nt++) {
                const int n0 = Nb + wn * 32 + nt * 8 + tq * 2;
                const int seg = n0 >> 10, nn = n0 & 1023;
                const float* bp = seg == 0 ? b0p : (seg == 1 ? b1p : b2p);
                const int hh = nn >> 6, dk = nn & 63;
                const float bb0 = bp[hh * 64 + dk], bb1 = bp[hh * 64 + dk + 1];
                const float alpha = (seg == 0) ? 0.125f : 1.f;
#pragma unroll
                for (int half = 0; half < 2; half++) {
                    const int r = wm * 64 + mt * 16 + gq + half * 8;
                    float v0 = (acc[mt][nt][half * 2 + 0] + bb0) * alpha;
                    float v1 = (acc[mt][nt][half * 2 + 1] + bb1) * alpha;
                    *(__half2*)&ep[r * 136 + wn * 32 + nt * 8 + tq * 2] =
                        __floats2half2_rn(v0, v1);
                }
            }
        }
        __syncthreads();
        const int bidx = Rb >> 10, sbase = Rb & 1023;
        for (int c = tid; c < 2048; c += 256) {
            const int r = c >> 4, s16 = c & 15;
            uint4 val = *(uint4*)&ep[r * 136 + s16 * 8];
            const int n = Nb + s16 * 8;
            const int seg = n >> 10, nn = n & 1023;
            const int hh = nn >> 6, dk = nn & 63;
            __half* dst = seg == 0 ? (__half*)C0 : (seg == 1 ? (__half*)C1 : (__half*)C2);
            *(uint4*)&dst[(((bidx * 16 + hh) << 10) + sbase + r) * 64 + dk] = val;
        }
        return;
    }

#pragma unroll
    for (int mt = 0; mt < 4; mt++) {
#pragma unroll
        for (int nt = 0; nt < 4; nt++) {
            const int m0 = Rb + wm * 64 + mt * 16 + gq;
            const int n0 = Nb + wn * 32 + nt * 8 + tq * 2;
            const float bb0 = b0p ? b0p[n0] : 0.f;
            const float bb1 = b0p ? b0p[n0 + 1] : 0.f;
#pragma unroll
            for (int half = 0; half < 2; half++) {
                const int m = m0 + half * 8;
                float v0 = acc[mt][nt][half * 2 + 0] + bb0;
                float v1 = acc[mt][nt][half * 2 + 1] + bb1;
                if (relu) { v0 = fmaxf(v0, 0.f); v1 = fmaxf(v1, 0.f); }
                *(__half2*)((__half*)C0 + m * N + n0) = __floats2half2_rn(v0, v1);
            }
        }
    }
}

// ---------------- fp16 flash attention v3 (exact R12/R14) ----------------
#define QST 72
#define PST 136
#define OFF_K  (128*QST)
#define OFF_V0 (2*128*QST)
#define VBUF   (128*QST)
#define OFF_P  (4*128*QST)
#define FL_SMH (OFF_P + 128*PST)
__global__ void __launch_bounds__(256, 2)
flash_h(const __half* __restrict__ Qg, const __half* __restrict__ Kg,
        const __half* __restrict__ Vg, __half* __restrict__ O)
{
    extern __shared__ __half sm[];
    const unsigned smB = (unsigned)__cvta_generic_to_shared(sm);
    const unsigned sQ = smB, sK = smB + OFF_K * 2;
    const unsigned sV0 = smB + OFF_V0 * 2, sP = smB + OFF_P * 2;

    const int tid = threadIdx.x, lane = tid & 31, wid = tid >> 5;
    const int tq = lane & 3, gq = lane >> 2;
    const int lr = lane & 15, lh = (lane >> 4) << 3;
    const int z = blockIdx.y, qt = blockIdx.x;

    const __half* Qp = Qg + (z * 1024 + qt * 128) * 64;
    const __half* Kp = Kg + z * 1024 * 64;
    const __half* Vp = Vg + z * 1024 * 64;

    auto stageT = [&](const __half* src, int kt, unsigned dst) {
#pragma unroll
        for (int i = 0; i < 4; i++) {
            const int c = tid + 256 * i;
            const int row = c >> 3, cc = (c & 7) * 8;
            cp16(dst + (row * QST + cc) * 2, src + (kt * 128 + row) * 64 + cc);
        }
    };

#pragma unroll
    for (int i = 0; i < 4; i++) {
        const int c = tid + 256 * i;
        const int row = c >> 3, cc = (c & 7) * 8;
        cp16(sQ + (row * QST + cc) * 2, Qp + row * 64 + cc);
    }
    stageT(Kp, 0, sK);
    stageT(Vp, 0, sV0);
    {
        const int buf = tid >> 7, row = tid & 127;
        uint4 ones = make_uint4(0x00003C00u, 0u, 0u, 0u);
        *(uint4*)(sm + OFF_V0 + buf * VBUF + row * QST + 64) = ones;
    }
    cp_commit(); cp_wait0();
    __syncthreads();

    float oacc[9][4];
#pragma unroll
    for (int i = 0; i < 9; i++)
#pragma unroll
        for (int j = 0; j < 4; j++) oacc[i][j] = 0.f;
    float mrow0 = -1e30f, mrow1 = -1e30f;

    const unsigned aQbase = sQ + ((wid * 16 + lr) * QST + lh) * 2;
    const unsigned aPbase = sP + ((wid * 16 + lr) * PST + lh) * 2;
    const int vrow = (lane & 7) + ((lane >> 3) & 1) * 8;
    const int vcol = (lane >> 4) << 3;

    for (int kt = 0; kt < 8; kt++) {
        const unsigned sV = sV0 + (kt & 1) * (VBUF * 2);

        float sacc[16][4];
#pragma unroll
        for (int i = 0; i < 16; i++)
#pragma unroll
            for (int j = 0; j < 4; j++) sacc[i][j] = 0.f;
#pragma unroll
        for (int k16 = 0; k16 < 4; k16++) {
            const int kb = k16 * 32;
            unsigned a[4];
            ldm_x4(a[0], a[1], a[2], a[3], aQbase + kb);
#pragma unroll
            for (int ntp = 0; ntp < 8; ntp++) {
                unsigned t0, t1, t2, t3;
                ldm_x4(t0, t1, t2, t3, sK + ((ntp * 16 + lr) * QST) * 2 + lh * 2 + kb);
                unsigned b0[2] = { t0, t2 }, b1[2] = { t1, t3 };
                mma16(sacc[2 * ntp],     a, b0);
                mma16(sacc[2 * ntp + 1], a, b1);
            }
        }

        __syncthreads();
        if (kt < 7) {
            stageT(Kp, kt + 1, sK);
            stageT(Vp, kt + 1, sV0 + ((kt + 1) & 1) * (VBUF * 2));
            cp_commit();
        }

        float m0 = -1e30f, m1 = -1e30f;
#pragma unroll
        for (int nt = 0; nt < 16; nt++) {
            m0 = fmaxf(m0, fmaxf(sacc[nt][0], sacc[nt][1]));
            m1 = fmaxf(m1, fmaxf(sacc[nt][2], sacc[nt][3]));
        }
        m0 = fmaxf(m0, __shfl_xor_sync(0xffffffffu, m0, 1));
        m0 = fmaxf(m0, __shfl_xor_sync(0xffffffffu, m0, 2));
        m1 = fmaxf(m1, __shfl_xor_sync(0xffffffffu, m1, 1));
        m1 = fmaxf(m1, __shfl_xor_sync(0xffffffffu, m1, 2));
        const float mn0 = fmaxf(mrow0, m0), mn1 = fmaxf(mrow1, m1);
        const float sc0 = __expf(mrow0 - mn0), sc1 = __expf(mrow1 - mn1);
        mrow0 = mn0; mrow1 = mn1;

        const float L2E = 1.44269504f;
        const float nm0 = mn0 * L2E, nm1 = mn1 * L2E;
        const unsigned pAddr = sP + ((wid * 16 + lr) * PST) * 2;
#pragma unroll
        for (int nt = 0; nt < 16; nt++) {
            const float y0 = fmaf(sacc[nt][0], L2E, -nm0);
            const float y1 = fmaf(sacc[nt][1], L2E, -nm0);
            const float y2 = fmaf(sacc[nt][2], L2E, -nm1);
            const float y3 = fmaf(sacc[nt][3], L2E, -nm1);
            __half2 h01 = __floats2half2_rn(y0, y1);
            __half2 h23 = __floats2half2_rn(y2, y3);
            stm_x2(pAddr + nt * 16, ex2h2(*(unsigned*)&h01), ex2h2(*(unsigned*)&h23));
        }
#pragma unroll
        for (int nt = 0; nt < 9; nt++) {
            oacc[nt][0] *= sc0; oacc[nt][1] *= sc0;
            oacc[nt][2] *= sc1; oacc[nt][3] *= sc1;
        }
        __syncwarp();

#pragma unroll
        for (int k16 = 0; k16 < 8; k16++) {
            const int k0 = k16 * 16;
            unsigned a[4];
            ldm_x4(a[0], a[1], a[2], a[3], aPbase + k16 * 32);
#pragma unroll
            for (int dk4 = 0; dk4 < 4; dk4++) {
                unsigned t0, t1, t2, t3;
                ldm_x4t(t0, t1, t2, t3,
                        sV + ((k0 + vrow) * QST + dk4 * 16 + vcol) * 2);
                unsigned b0[2] = { t0, t1 }, b1[2] = { t2, t3 };
                mma16(oacc[2 * dk4],     a, b0);
                mma16(oacc[2 * dk4 + 1], a, b1);
            }
            {
                unsigned t0, t1;
                ldm_x2t(t0, t1, sV + ((k0 + lr) * QST + 64) * 2);
                unsigned b[2] = { t0, t1 };
                mma16(oacc[8], a, b);
            }
        }

        if (kt < 7) {
            cp_wait0();
            __syncthreads();
        }
    }

    const float l0 = __shfl_sync(0xffffffffu, oacc[8][0], lane & ~3);
    const float l1 = __shfl_sync(0xffffffffu, oacc[8][2], lane & ~3);
    const float i0 = 1.f / l0, i1 = 1.f / l1;
    const int b = z >> 4, h = z & 15;
    const int s0 = qt * 128 + wid * 16 + gq;
#pragma unroll
    for (int nt = 0; nt < 8; nt++) {
        const int col = h * 64 + nt * 8 + 2 * tq;
        *(__half2*)&O[(b * 1024 + s0) * 1024 + col] =
            __floats2half2_rn(oacc[nt][0] * i0, oacc[nt][1] * i0);
        *(__half2*)&O[(b * 1024 + s0 + 8) * 1024 + col] =
            __floats2half2_rn(oacc[nt][2] * i1, oacc[nt][3] * i1);
    }
}

// ---------------- residual + LayerNorm (exact R14) ----------------
template<class TX>
__global__ void __launch_bounds__(256)
add_ln_kernel(const TX* __restrict__ x, const __half* __restrict__ t,
              const float* __restrict__ gw, const float* __restrict__ bw,
              float* __restrict__ out_f, __half* __restrict__ out_h)
{
    __shared__ float r1[8], r2[8];
    const int base = blockIdx.x * 1024;
    const int tid = threadIdx.x;
    __half2 th0 = *(const __half2*)(t + base + tid * 4);
    __half2 th1 = *(const __half2*)(t + base + tid * 4 + 2);
    float4 tv;
    { float2 a = __half22float2(th0), b = __half22float2(th1);
      tv.x = a.x; tv.y = a.y; tv.z = b.x; tv.w = b.y; }

    float s = tv.x + tv.y + tv.z + tv.w;
    float q = tv.x * tv.x + tv.y * tv.y + tv.z * tv.z + tv.w * tv.w;
#pragma unroll
    for (int o = 16; o; o >>= 1) {
        s += __shfl_xor_sync(0xffffffffu, s, o);
        q += __shfl_xor_sync(0xffffffffu, q, o);
    }
    if ((tid & 31) == 0) { r1[tid >> 5] = s; r2[tid >> 5] = q; }
    __syncthreads();
    if (tid < 32) {
        float ss = (tid < 8) ? r1[tid] : 0.f;
        float qq = (tid < 8) ? r2[tid] : 0.f;
#pragma unroll
        for (int o = 4; o; o >>= 1) {
            ss += __shfl_xor_sync(0xffffffffu, ss, o);
            qq += __shfl_xor_sync(0xffffffffu, qq, o);
        }
        if (tid == 0) { r1[0] = ss; r2[0] = qq; }
    }
    __syncthreads();
    const float mean = r1[0] * (1.f / 1024.f);
    const float var  = r2[0] * (1.f / 1024.f) - mean * mean;
    const float rstd = rsqrtf(var + 1e-5f);

    float4 xv;
    if (sizeof(TX) == 4) {
        xv = *(const float4*)((const float*)x + base + tid * 4);
    } else {
        __half2 xh0 = *(const __half2*)((const __half*)x + base + tid * 4);
        __half2 xh1 = *(const __half2*)((const __half*)x + base + tid * 4 + 2);
        float2 a = __half22float2(xh0), b = __half22float2(xh1);
        xv.x = a.x; xv.y = a.y; xv.z = b.x; xv.w = b.y;
    }
    float4 gv = *(const float4*)(gw + tid * 4);
    float4 bv = *(const float4*)(bw + tid * 4);
    float4 o;
    o.x = xv.x + (tv.x - mean) * rstd * gv.x + bv.x;
    o.y = xv.y + (tv.y - mean) * rstd * gv.y + bv.y;
    o.z = xv.z + (tv.z - mean) * rstd * gv.z + bv.z;
    o.w = xv.w + (tv.w - mean) * rstd * gv.w + bv.w;
    if (out_f)
        *(float4*)(out_f + base + tid * 4) = o;
    if (out_h) {
        __half2* oh = (__half2*)(out_h + base + tid * 4);
        oh[0] = __floats2half2_rn(o.x, o.y);
        oh[1] = __floats2half2_rn(o.z, o.w);
    }
}

// ---------------- launch ----------------
template<class T>
static T* sym_addr(const void* s) {
    void* p = nullptr;
    cudaGetSymbolAddress(&p, s);
    return (T*)p;
}

extern "C" void kernel_launch(void* const* d_in, const int* in_sizes, int n_in,
                              void* d_out, int out_size)
{
    (void)in_sizes; (void)n_in; (void)out_size;
    const float* x   = (const float*)d_in[0];
    const float* Wq  = (const float*)d_in[1];
    const float* bq  = (const float*)d_in[2];
    const float* Wk  = (const float*)d_in[3];
    const float* bk  = (const float*)d_in[4];
    const float* Wv  = (const float*)d_in[5];
    const float* bv  = (const float*)d_in[6];
    const float* Wo  = (const float*)d_in[7];
    const float* bo  = (const float*)d_in[8];
    const float* W1  = (const float*)d_in[9];
    const float* b1  = (const float*)d_in[10];
    const float* W2  = (const float*)d_in[11];
    const float* b2  = (const float*)d_in[12];
    const float* g1  = (const float*)d_in[13];
    const float* be1 = (const float*)d_in[14];
    const float* g2  = (const float*)d_in[15];
    const float* be2 = (const float*)d_in[16];
    float* out = (float*)d_out;

    __half* xh   = sym_addr<__half>(g_xh);
    __half* wqkv = sym_addr<__half>(g_wqkv);
    __half* wo   = sym_addr<__half>(g_wo);
    __half* w1   = sym_addr<__half>(g_w1);
    __half* w2   = sym_addr<__half>(g_w2);
    __half* q    = sym_addr<__half>(g_q);
    __half* k    = sym_addr<__half>(g_k);
    __half* v    = sym_addr<__half>(g_v);
    __half* oc   = sym_addr<__half>(g_oc);
    __half* at   = sym_addr<__half>(g_at);
    __half* x1h  = sym_addr<__half>(g_x1h);
    __half* ff   = sym_addr<__half>(g_ff);
    __half* ps   = sym_addr<__half>(g_ps);

    static cudaStream_t s2 = nullptr;
    static cudaEvent_t evFork = nullptr, evJoin = nullptr;
    if (!s2) {
        cudaStreamCreateWithFlags(&s2, cudaStreamNonBlocking);
        cudaEventCreateWithFlags(&evFork, cudaEventDisableTiming);
        cudaEventCreateWithFlags(&evJoin, cudaEventDisableTiming);
    }

    const int FSM = FL_SMH * 2;
    cudaFuncSetAttribute(gemm_h2<0>, cudaFuncAttributeMaxDynamicSharedMemorySize, G2SM);
    cudaFuncSetAttribute(gemm_h2<1>, cudaFuncAttributeMaxDynamicSharedMemorySize, G2SM);
    cudaFuncSetAttribute(flash_h,    cudaFuncAttributeMaxDynamicSharedMemorySize, FSM);

    const dim3 blk(256);

    // cvt_a runs alone at full bandwidth (QKV dependency)
    cvt_a<<<3584, blk>>>(x, Wq, Wk, Wv, xh, wqkv);

    // fork AFTER cvt_a: cvt_b overlaps QKV GEMM + flash (DRAM ~idle there)
    cudaEventRecord(evFork, 0);
    cudaStreamWaitEvent(s2, evFork, 0);
    cvt_b<<<4608, blk, 0, s2>>>(Wo, W1, W2, wo, w1, w2);
    cudaEventRecord(evJoin, s2);

    gemm_h2<1><<<dim3(24, 32), blk, G2SM>>>(xh, wqkv, bq, bk, bv,
                                            q, k, v, 4096, 3072, 1024, 0);
    flash_h<<<dim3(8, 64), blk, FSM>>>(q, k, v, oc);

    // join before first consumer of wo/w1/w2
    cudaStreamWaitEvent(0, evJoin, 0);

    gemm_h2<0><<<dim3(8, 32), blk, G2SM>>>(oc, wo, bo, nullptr, nullptr,
                                           at, nullptr, nullptr, 4096, 1024, 1024, 0);
    add_ln_kernel<float><<<4096, blk>>>(x, at, g1, be1, nullptr, x1h);

    gemm_h2<0><<<dim3(32, 32), blk, G2SM>>>(x1h, w1, b1, nullptr, nullptr,
                                            ff, nullptr, nullptr, 4096, 4096, 1024, 1);
    gemm_h2<0><<<dim3(8, 32), blk, G2SM>>>(ff, w2, b2, nullptr, nullptr,
                                           ps, nullptr, nullptr, 4096, 1024, 4096, 0);

    add_ln_kernel<__half><<<4096, blk>>>(x1h, ps, g2, be2, out, nullptr);
}

// round 17
// speedup vs baseline: 1.0273x; 1.0216x over previous
#include <cuda_runtime.h>
#include <cuda_fp16.h>

#define BB 4
#define SS 1024
#define DD 1024
#define HH 16
#define DKC 64
#define DFF 4096

// ---------------- scratch ----------------
__device__ __half g_xh  [BB*SS*DD];
__device__ __half g_wqkv[DD*3*DD];          // [k=1024 d][n=3072: seg*1024+h*64+dk]
__device__ __half g_wo  [DD*DD];            // [K,N]
__device__ __half g_w1  [DD*DFF];
__device__ __half g_w2  [DFF*DD];
__device__ __half g_q   [BB*HH*SS*DKC];     // [z][s][dk]
__device__ __half g_k   [BB*HH*SS*DKC];
__device__ __half g_v   [BB*HH*SS*DKC];
__device__ __half g_oc  [BB*SS*DD];
__device__ __half g_at  [BB*SS*DD];
__device__ __half g_x1h [BB*SS*DD];
__device__ __half g_ff  [BB*SS*DFF];
__device__ __half g_ps  [BB*SS*DD];

// ---------------- asm helpers ----------------
__device__ __forceinline__ void cp16(unsigned dst, const void* src) {
    asm volatile("cp.async.cg.shared.global [%0], [%1], 16;" :: "r"(dst), "l"(src));
}
__device__ __forceinline__ void cp_commit() { asm volatile("cp.async.commit_group;" ::: "memory"); }
__device__ __forceinline__ void cp_wait0()  { asm volatile("cp.async.wait_group 0;" ::: "memory"); }
__device__ __forceinline__ void cp_wait1()  { asm volatile("cp.async.wait_group 1;" ::: "memory"); }

__device__ __forceinline__ void ldm_x4(unsigned& r0, unsigned& r1, unsigned& r2, unsigned& r3, unsigned addr) {
    asm volatile("ldmatrix.sync.aligned.m8n8.x4.shared.b16 {%0,%1,%2,%3}, [%4];"
                 : "=r"(r0), "=r"(r1), "=r"(r2), "=r"(r3) : "r"(addr));
}
__device__ __forceinline__ void ldm_x4t(unsigned& r0, unsigned& r1, unsigned& r2, unsigned& r3, unsigned addr) {
    asm volatile("ldmatrix.sync.aligned.m8n8.x4.trans.shared.b16 {%0,%1,%2,%3}, [%4];"
                 : "=r"(r0), "=r"(r1), "=r"(r2), "=r"(r3) : "r"(addr));
}
__device__ __forceinline__ void ldm_x2t(unsigned& r0, unsigned& r1, unsigned addr) {
    asm volatile("ldmatrix.sync.aligned.m8n8.x2.trans.shared.b16 {%0,%1}, [%2];"
                 : "=r"(r0), "=r"(r1) : "r"(addr));
}
__device__ __forceinline__ void mma16(float* c, const unsigned* a, const unsigned* b) {
    asm volatile(
        "mma.sync.aligned.m16n8k16.row.col.f32.f16.f16.f32 "
        "{%0,%1,%2,%3},{%4,%5,%6,%7},{%8,%9},{%0,%1,%2,%3};"
        : "+f"(c[0]), "+f"(c[1]), "+f"(c[2]), "+f"(c[3])
        : "r"(a[0]), "r"(a[1]), "r"(a[2]), "r"(a[3]), "r"(b[0]), "r"(b[1]));
}
__device__ __forceinline__ unsigned ex2h2(unsigned x) {
    unsigned r;
    asm("ex2.approx.f16x2 %0, %1;" : "=r"(r) : "r"(x));
    return r;
}

// ---------------- fused streaming conversion (exact R14) ----------------
__global__ void __launch_bounds__(256)
cvt_all(const float* __restrict__ x,
        const float* __restrict__ Wq, const float* __restrict__ Wk,
        const float* __restrict__ Wv, const float* __restrict__ Wo,
        const float* __restrict__ W1, const float* __restrict__ W2,
        __half* __restrict__ xh, __half* __restrict__ wqkv,
        __half* __restrict__ wo, __half* __restrict__ w1, __half* __restrict__ w2)
{
    const int tid = threadIdx.x;
    int b = blockIdx.x;

    if (b < 2048) {
        const int i = (b * 256 + tid) * 8;
        float4 v0 = *(const float4*)(x + i);
        float4 v1 = *(const float4*)(x + i + 4);
        __half2* o = (__half2*)(xh + i);
        o[0] = __floats2half2_rn(v0.x, v0.y);
        o[1] = __floats2half2_rn(v0.z, v0.w);
        o[2] = __floats2half2_rn(v1.x, v1.y);
        o[3] = __floats2half2_rn(v1.z, v1.w);
        return;
    }
    b -= 2048;
    if (b < 1536) {
        const int c = b * 256 + tid;
        const int seg = c >> 17;
        const int r = c & 131071;
        const int d = r >> 7, h = (r >> 3) & 15, dk8 = r & 7;
        const float* src = (seg == 0 ? Wq : (seg == 1 ? Wk : Wv)) + h * 65536 + d * 64 + dk8 * 8;
        float4 a = *(const float4*)src;
        float4 bb = *(const float4*)(src + 4);
        __half2* o = (__half2*)(wqkv + d * 3072 + seg * 1024 + h * 64 + dk8 * 8);
        o[0] = __floats2half2_rn(a.x, a.y);
        o[1] = __floats2half2_rn(a.z, a.w);
        o[2] = __floats2half2_rn(bb.x, bb.y);
        o[3] = __floats2half2_rn(bb.z, bb.w);
        return;
    }
    b -= 1536;
    const float* src; __half* dst;
    if (b < 512)       { src = Wo; dst = wo; }
    else if (b < 2560) { b -= 512; src = W1; dst = w1; }
    else               { b -= 2560; src = W2; dst = w2; }
    const int i = (b * 256 + tid) * 8;
    float4 v0 = *(const float4*)(src + i);
    float4 v1 = *(const float4*)(src + i + 4);
    __half2* o = (__half2*)(dst + i);
    o[0] = __floats2half2_rn(v0.x, v0.y);
    o[1] = __floats2half2_rn(v0.z, v0.w);
    o[2] = __floats2half2_rn(v1.x, v1.y);
    o[3] = __floats2half2_rn(v1.z, v1.w);
}

// ---------------- swizzles ----------------
__device__ __forceinline__ unsigned tswz(int row, int kbyte) {
    return (unsigned)(row * 128 + ((kbyte ^ ((row & 7) << 4)) & 127) + (kbyte & ~127));
}
__device__ __forceinline__ unsigned swz256(int row, int cb) {
    return (unsigned)(row * 256 + (cb & 128) + ((cb & 127) ^ ((row & 7) << 4)));
}

// ---------------- fp16 GEMM (exact R12/R14) ----------------
#define STG_B 32768
#define G2SM  (3*STG_B)

template<int EPI>
__global__ void __launch_bounds__(256, 2)
gemm_h2(const __half* __restrict__ A, const __half* __restrict__ B,
        const float* __restrict__ b0p, const float* __restrict__ b1p,
        const float* __restrict__ b2p, void* __restrict__ C0,
        void* __restrict__ C1, void* __restrict__ C2,
        int M, int N, int K, int relu)
{
    extern __shared__ char dsm[];
    const unsigned smB = (unsigned)__cvta_generic_to_shared(dsm);

    const int tid = threadIdx.x, lane = tid & 31, wid = tid >> 5;
    const int wm = wid & 1, wn = wid >> 1;
    const int Rb = blockIdx.y * 128;
    const int Nb = blockIdx.x * 128;
    const int nS = K >> 6;

    const int crow = tid >> 3, ckc = (tid & 7) * 16;
    const int lr = lane & 15, lhb = ((lane >> 4) << 4);
    const int vrow = (lane & 7) + ((lane >> 3) & 1) * 8;
    const int vcol = (lane >> 4) << 3;

    auto issue = [&](int it) {
        const unsigned sA = smB + (it % 3) * STG_B;
        const unsigned sB = sA + 16384;
        const __half* Ap = A + (Rb + crow) * K + it * 64 + ckc / 2;
#pragma unroll
        for (int i = 0; i < 4; i++)
            cp16(sA + tswz(crow + 32 * i, ckc), Ap + 32 * i * K);
#pragma unroll
        for (int i = 0; i < 4; i++) {
            const int c = tid + 256 * i;
            const int row = c >> 4, cb = (c & 15) * 16;
            cp16(sB + swz256(row, cb), B + (it * 64 + row) * N + Nb + (c & 15) * 8);
        }
    };

    float acc[4][4][4];
#pragma unroll
    for (int i = 0; i < 4; i++)
#pragma unroll
        for (int j = 0; j < 4; j++)
#pragma unroll
            for (int r = 0; r < 4; r++) acc[i][j][r] = 0.f;

    issue(0); cp_commit();
    issue(1); cp_commit();

    for (int it = 0; it < nS; it++) {
        cp_wait1();
        __syncthreads();
        if (it + 2 < nS) issue(it + 2);
        cp_commit();

        const unsigned sA = smB + (it % 3) * STG_B;
        const unsigned sB = sA + 16384;
#pragma unroll
        for (int s = 0; s < 4; s++) {
            const int kb = s * 32;
            const int ks = s * 16;
            unsigned af[4][4], bf[2][4];
#pragma unroll
            for (int mt = 0; mt < 4; mt++)
                ldm_x4(af[mt][0], af[mt][1], af[mt][2], af[mt][3],
                       sA + tswz(wm * 64 + mt * 16 + lr, kb + lhb));
#pragma unroll
            for (int nt2 = 0; nt2 < 2; nt2++)
                ldm_x4t(bf[nt2][0], bf[nt2][1], bf[nt2][2], bf[nt2][3],
                        sB + swz256(ks + vrow, (wn * 32 + nt2 * 16 + vcol) * 2));
#pragma unroll
            for (int mt = 0; mt < 4; mt++)
#pragma unroll
                for (int nt = 0; nt < 4; nt++) {
                    unsigned b[2] = { bf[nt >> 1][(nt & 1) * 2], bf[nt >> 1][(nt & 1) * 2 + 1] };
                    mma16(acc[mt][nt], af[mt], b);
                }
        }
    }

    const int tq = lane & 3, gq = lane >> 2;

    if (EPI == 1) {
        __syncthreads();
        __half* ep = (__half*)dsm;
#pragma unroll
        for (int mt = 0; mt < 4; mt++) {
#pragma unroll
            for (int nt = 0; nt < 4; nt++) {
                const int n0 = Nb + wn * 32 + nt * 8 + tq * 2;
                const int seg = n0 >> 10, nn = n0 & 1023;
                const float* bp = seg == 0 ? b0p : (seg == 1 ? b1p : b2p);
                const int hh = nn >> 6, dk = nn & 63;
                const float bb0 = bp[hh * 64 + dk], bb1 = bp[hh * 64 + dk + 1];
                const float alpha = (seg == 0) ? 0.125f : 1.f;
#pragma unroll
                for (int half = 0; half < 2; half++) {
                    const int r = wm * 64 + mt * 16 + gq + half * 8;
                    float v0 = (acc[mt][nt][half * 2 + 0] + bb0) * alpha;
                    float v1 = (acc[mt][nt][half * 2 + 1] + bb1) * alpha;
                    *(__half2*)&ep[r * 136 + wn * 32 + nt * 8 + tq * 2] =
                        __floats2half2_rn(v0, v1);
                }
            }
        }
        __syncthreads();
        const int bidx = Rb >> 10, sbase = Rb & 1023;
        for (int c = tid; c < 2048; c += 256) {
            const int r = c >> 4, s16 = c & 15;
            uint4 val = *(uint4*)&ep[r * 136 + s16 * 8];
            const int n = Nb + s16 * 8;
            const int seg = n >> 10, nn = n & 1023;
            const int hh = nn >> 6, dk = nn & 63;
            __half* dst = seg == 0 ? (__half*)C0 : (seg == 1 ? (__half*)C1 : (__half*)C2);
            *(uint4*)&dst[(((bidx * 16 + hh) << 10) + sbase + r) * 64 + dk] = val;
        }
        return;
    }

#pragma unroll
    for (int mt = 0; mt < 4; mt++) {
#pragma unroll
        for (int nt = 0; nt < 4; nt++) {
            const int m0 = Rb + wm * 64 + mt * 16 + gq;
            const int n0 = Nb + wn * 32 + nt * 8 + tq * 2;
            const float bb0 = b0p ? b0p[n0] : 0.f;
            const float bb1 = b0p ? b0p[n0 + 1] : 0.f;
#pragma unroll
            for (int half = 0; half < 2; half++) {
                const int m = m0 + half * 8;
                float v0 = acc[mt][nt][half * 2 + 0] + bb0;
                float v1 = acc[mt][nt][half * 2 + 1] + bb1;
                if (relu) { v0 = fmaxf(v0, 0.f); v1 = fmaxf(v1, 0.f); }
                *(__half2*)((__half*)C0 + m * N + n0) = __floats2half2_rn(v0, v1);
            }
        }
    }
}

// ---------------- fp16 flash attention v4: P stays in registers ----------------
// m16n8k16 C-fragment layout == next mma's A-fragment layout (packed f16x2),
// so P never touches smem. sP buffer, 16 STSM + 8 LDSM per warp/kt removed.
#define QST 72
#define OFF_K  (128*QST)
#define OFF_V0 (2*128*QST)
#define VBUF   (128*QST)
#define FL_SMH (4*128*QST)          // 36864 halfs = 73728 B
__global__ void __launch_bounds__(256, 2)
flash_h(const __half* __restrict__ Qg, const __half* __restrict__ Kg,
        const __half* __restrict__ Vg, __half* __restrict__ O)
{
    extern __shared__ __half sm[];
    const unsigned smB = (unsigned)__cvta_generic_to_shared(sm);
    const unsigned sQ = smB, sK = smB + OFF_K * 2;
    const unsigned sV0 = smB + OFF_V0 * 2;

    const int tid = threadIdx.x, lane = tid & 31, wid = tid >> 5;
    const int tq = lane & 3, gq = lane >> 2;
    const int lr = lane & 15, lh = (lane >> 4) << 3;
    const int z = blockIdx.y, qt = blockIdx.x;

    const __half* Qp = Qg + (z * 1024 + qt * 128) * 64;
    const __half* Kp = Kg + z * 1024 * 64;
    const __half* Vp = Vg + z * 1024 * 64;

    auto stageT = [&](const __half* src, int kt, unsigned dst) {
#pragma unroll
        for (int i = 0; i < 4; i++) {
            const int c = tid + 256 * i;
            const int row = c >> 3, cc = (c & 7) * 8;
            cp16(dst + (row * QST + cc) * 2, src + (kt * 128 + row) * 64 + cc);
        }
    };

#pragma unroll
    for (int i = 0; i < 4; i++) {
        const int c = tid + 256 * i;
        const int row = c >> 3, cc = (c & 7) * 8;
        cp16(sQ + (row * QST + cc) * 2, Qp + row * 64 + cc);
    }
    stageT(Kp, 0, sK);
    stageT(Vp, 0, sV0);
    {
        const int buf = tid >> 7, row = tid & 127;
        uint4 ones = make_uint4(0x00003C00u, 0u, 0u, 0u);
        *(uint4*)(sm + OFF_V0 + buf * VBUF + row * QST + 64) = ones;
    }
    cp_commit(); cp_wait0();
    __syncthreads();

    float oacc[9][4];
#pragma unroll
    for (int i = 0; i < 9; i++)
#pragma unroll
        for (int j = 0; j < 4; j++) oacc[i][j] = 0.f;
    float mrow0 = -1e30f, mrow1 = -1e30f;

    const unsigned aQbase = sQ + ((wid * 16 + lr) * QST + lh) * 2;
    const int vrow = (lane & 7) + ((lane >> 3) & 1) * 8;
    const int vcol = (lane >> 4) << 3;

    for (int kt = 0; kt < 8; kt++) {
        const unsigned sV = sV0 + (kt & 1) * (VBUF * 2);

        // ---- S = Q @ K^T ----
        float sacc[16][4];
#pragma unroll
        for (int i = 0; i < 16; i++)
#pragma unroll
            for (int j = 0; j < 4; j++) sacc[i][j] = 0.f;
#pragma unroll
        for (int k16 = 0; k16 < 4; k16++) {
            const int kb = k16 * 32;
            unsigned a[4];
            ldm_x4(a[0], a[1], a[2], a[3], aQbase + kb);
#pragma unroll
            for (int ntp = 0; ntp < 8; ntp++) {
                unsigned t0, t1, t2, t3;
                ldm_x4(t0, t1, t2, t3, sK + ((ntp * 16 + lr) * QST) * 2 + lh * 2 + kb);
                unsigned b0[2] = { t0, t2 }, b1[2] = { t1, t3 };
                mma16(sacc[2 * ntp],     a, b0);
                mma16(sacc[2 * ntp + 1], a, b1);
            }
        }

        __syncthreads();
        if (kt < 7) {
            stageT(Kp, kt + 1, sK);
            stageT(Vp, kt + 1, sV0 + ((kt + 1) & 1) * (VBUF * 2));
            cp_commit();
        }

        // ---- online softmax, P kept in registers as A-fragments ----
        float m0 = -1e30f, m1 = -1e30f;
#pragma unroll
        for (int nt = 0; nt < 16; nt++) {
            m0 = fmaxf(m0, fmaxf(sacc[nt][0], sacc[nt][1]));
            m1 = fmaxf(m1, fmaxf(sacc[nt][2], sacc[nt][3]));
        }
        m0 = fmaxf(m0, __shfl_xor_sync(0xffffffffu, m0, 1));
        m0 = fmaxf(m0, __shfl_xor_sync(0xffffffffu, m0, 2));
        m1 = fmaxf(m1, __shfl_xor_sync(0xffffffffu, m1, 1));
        m1 = fmaxf(m1, __shfl_xor_sync(0xffffffffu, m1, 2));
        const float mn0 = fmaxf(mrow0, m0), mn1 = fmaxf(mrow1, m1);
        const float sc0 = __expf(mrow0 - mn0), sc1 = __expf(mrow1 - mn1);
        mrow0 = mn0; mrow1 = mn1;

        const float L2E = 1.44269504f;
        const float nm0 = mn0 * L2E, nm1 = mn1 * L2E;
        unsigned pexp[16][2];
#pragma unroll
        for (int nt = 0; nt < 16; nt++) {
            const float y0 = fmaf(sacc[nt][0], L2E, -nm0);
            const float y1 = fmaf(sacc[nt][1], L2E, -nm0);
            const float y2 = fmaf(sacc[nt][2], L2E, -nm1);
            const float y3 = fmaf(sacc[nt][3], L2E, -nm1);
            __half2 h01 = __floats2half2_rn(y0, y1);
            __half2 h23 = __floats2half2_rn(y2, y3);
            pexp[nt][0] = ex2h2(*(unsigned*)&h01);
            pexp[nt][1] = ex2h2(*(unsigned*)&h23);
        }
#pragma unroll
        for (int nt = 0; nt < 9; nt++) {
            oacc[nt][0] *= sc0; oacc[nt][1] *= sc0;
            oacc[nt][2] *= sc1; oacc[nt][3] *= sc1;
        }

        // ---- O(+l) += P @ [V | 1], A operands direct from pexp ----
#pragma unroll
        for (int k16 = 0; k16 < 8; k16++) {
            const int k0 = k16 * 16;
            unsigned a[4] = { pexp[2 * k16][0], pexp[2 * k16][1],
                              pexp[2 * k16 + 1][0], pexp[2 * k16 + 1][1] };
#pragma unroll
            for (int dk4 = 0; dk4 < 4; dk4++) {
                unsigned t0, t1, t2, t3;
                ldm_x4t(t0, t1, t2, t3,
                        sV + ((k0 + vrow) * QST + dk4 * 16 + vcol) * 2);
                unsigned b0[2] = { t0, t1 }, b1[2] = { t2, t3 };
                mma16(oacc[2 * dk4],     a, b0);
                mma16(oacc[2 * dk4 + 1], a, b1);
            }
            {
                unsigned t0, t1;
                ldm_x2t(t0, t1, sV + ((k0 + lr) * QST + 64) * 2);
                unsigned b[2] = { t0, t1 };
                mma16(oacc[8], a, b);
            }
        }

        if (kt < 7) {
            cp_wait0();
            __syncthreads();
        }
    }

    const float l0 = __shfl_sync(0xffffffffu, oacc[8][0], lane & ~3);
    const float l1 = __shfl_sync(0xffffffffu, oacc[8][2], lane & ~3);
    const float i0 = 1.f / l0, i1 = 1.f / l1;
    const int b = z >> 4, h = z & 15;
    const int s0 = qt * 128 + wid * 16 + gq;
#pragma unroll
    for (int nt = 0; nt < 8; nt++) {
        const int col = h * 64 + nt * 8 + 2 * tq;
        *(__half2*)&O[(b * 1024 + s0) * 1024 + col] =
            __floats2half2_rn(oacc[nt][0] * i0, oacc[nt][1] * i0);
        *(__half2*)&O[(b * 1024 + s0 + 8) * 1024 + col] =
            __floats2half2_rn(oacc[nt][2] * i1, oacc[nt][3] * i1);
    }
}

// ---------------- residual + LayerNorm (exact R14) ----------------
template<class TX>
__global__ void __launch_bounds__(256)
add_ln_kernel(const TX* __restrict__ x, const __half* __restrict__ t,
              const float* __restrict__ gw, const float* __restrict__ bw,
              float* __restrict__ out_f, __half* __restrict__ out_h)
{
    __shared__ float r1[8], r2[8];
    const int base = blockIdx.x * 1024;
    const int tid = threadIdx.x;
    __half2 th0 = *(const __half2*)(t + base + tid * 4);
    __half2 th1 = *(const __half2*)(t + base + tid * 4 + 2);
    float4 tv;
    { float2 a = __half22float2(th0), b = __half22float2(th1);
      tv.x = a.x; tv.y = a.y; tv.z = b.x; tv.w = b.y; }

    float s = tv.x + tv.y + tv.z + tv.w;
    float q = tv.x * tv.x + tv.y * tv.y + tv.z * tv.z + tv.w * tv.w;
#pragma unroll
    for (int o = 16; o; o >>= 1) {
        s += __shfl_xor_sync(0xffffffffu, s, o);
        q += __shfl_xor_sync(0xffffffffu, q, o);
    }
    if ((tid & 31) == 0) { r1[tid >> 5] = s; r2[tid >> 5] = q; }
    __syncthreads();
    if (tid < 32) {
        float ss = (tid < 8) ? r1[tid] : 0.f;
        float qq = (tid < 8) ? r2[tid] : 0.f;
#pragma unroll
        for (int o = 4; o; o >>= 1) {
            ss += __shfl_xor_sync(0xffffffffu, ss, o);
            qq += __shfl_xor_sync(0xffffffffu, qq, o);
        }
        if (tid == 0) { r1[0] = ss; r2[0] = qq; }
    }
    __syncthreads();
    const float mean = r1[0] * (1.f / 1024.f);
    const float var  = r2[0] * (1.f / 1024.f) - mean * mean;
    const float rstd = rsqrtf(var + 1e-5f);

    float4 xv;
    if (sizeof(TX) == 4) {
        xv = *(const float4*)((const float*)x + base + tid * 4);
    } else {
        __half2 xh0 = *(const __half2*)((const __half*)x + base + tid * 4);
        __half2 xh1 = *(const __half2*)((const __half*)x + base + tid * 4 + 2);
        float2 a = __half22float2(xh0), b = __half22float2(xh1);
        xv.x = a.x; xv.y = a.y; xv.z = b.x; xv.w = b.y;
    }
    float4 gv = *(const float4*)(gw + tid * 4);
    float4 bv = *(const float4*)(bw + tid * 4);
    float4 o;
    o.x = xv.x + (tv.x - mean) * rstd * gv.x + bv.x;
    o.y = xv.y + (tv.y - mean) * rstd * gv.y + bv.y;
    o.z = xv.z + (tv.z - mean) * rstd * gv.z + bv.z;
    o.w = xv.w + (tv.w - mean) * rstd * gv.w + bv.w;
    if (out_f)
        *(float4*)(out_f + base + tid * 4) = o;
    if (out_h) {
        __half2* oh = (__half2*)(out_h + base + tid * 4);
        oh[0] = __floats2half2_rn(o.x, o.y);
        oh[1] = __floats2half2_rn(o.z, o.w);
    }
}

// ---------------- launch ----------------
template<class T>
static T* sym_addr(const void* s) {
    void* p = nullptr;
    cudaGetSymbolAddress(&p, s);
    return (T*)p;
}

extern "C" void kernel_launch(void* const* d_in, const int* in_sizes, int n_in,
                              void* d_out, int out_size)
{
    (void)in_sizes; (void)n_in; (void)out_size;
    const float* x   = (const float*)d_in[0];
    const float* Wq  = (const float*)d_in[1];
    const float* bq  = (const float*)d_in[2];
    const float* Wk  = (const float*)d_in[3];
    const float* bk  = (const float*)d_in[4];
    const float* Wv  = (const float*)d_in[5];
    const float* bv  = (const float*)d_in[6];
    const float* Wo  = (const float*)d_in[7];
    const float* bo  = (const float*)d_in[8];
    const float* W1  = (const float*)d_in[9];
    const float* b1  = (const float*)d_in[10];
    const float* W2  = (const float*)d_in[11];
    const float* b2  = (const float*)d_in[12];
    const float* g1  = (const float*)d_in[13];
    const float* be1 = (const float*)d_in[14];
    const float* g2  = (const float*)d_in[15];
    const float* be2 = (const float*)d_in[16];
    float* out = (float*)d_out;

    __half* xh   = sym_addr<__half>(g_xh);
    __half* wqkv = sym_addr<__half>(g_wqkv);
    __half* wo   = sym_addr<__half>(g_wo);
    __half* w1   = sym_addr<__half>(g_w1);
    __half* w2   = sym_addr<__half>(g_w2);
    __half* q    = sym_addr<__half>(g_q);
    __half* k    = sym_addr<__half>(g_k);
    __half* v    = sym_addr<__half>(g_v);
    __half* oc   = sym_addr<__half>(g_oc);
    __half* at   = sym_addr<__half>(g_at);
    __half* x1h  = sym_addr<__half>(g_x1h);
    __half* ff   = sym_addr<__half>(g_ff);
    __half* ps   = sym_addr<__half>(g_ps);

    const int FSM = FL_SMH * 2;
    cudaFuncSetAttribute(gemm_h2<0>, cudaFuncAttributeMaxDynamicSharedMemorySize, G2SM);
    cudaFuncSetAttribute(gemm_h2<1>, cudaFuncAttributeMaxDynamicSharedMemorySize, G2SM);
    cudaFuncSetAttribute(flash_h,    cudaFuncAttributeMaxDynamicSharedMemorySize, FSM);

    const dim3 blk(256);

    cvt_all<<<8192, blk>>>(x, Wq, Wk, Wv, Wo, W1, W2,
                           xh, wqkv, wo, w1, w2);

    // fused QKV projection (q scaled by 1/8 in epilogue)
    gemm_h2<1><<<dim3(24, 32), blk, G2SM>>>(xh, wqkv, bq, bk, bv,
                                            q, k, v, 4096, 3072, 1024, 0);

    flash_h<<<dim3(8, 64), blk, FSM>>>(q, k, v, oc);

    // O projection -> fp16 at
    gemm_h2<0><<<dim3(8, 32), blk, G2SM>>>(oc, wo, bo, nullptr, nullptr,
                                           at, nullptr, nullptr, 4096, 1024, 1024, 0);
    add_ln_kernel<float><<<4096, blk>>>(x, at, g1, be1, nullptr, x1h);

    // FFN
    gemm_h2<0><<<dim3(32, 32), blk, G2SM>>>(x1h, w1, b1, nullptr, nullptr,
                                            ff, nullptr, nullptr, 4096, 4096, 1024, 1);
    gemm_h2<0><<<dim3(8, 32), blk, G2SM>>>(ff, w2, b2, nullptr, nullptr,
                                           ps, nullptr, nullptr, 4096, 1024, 4096, 0);

    add_ln_kernel<__half><<<4096, blk>>>(x1h, ps, g2, be2, out, nullptr);
}